// round 4
// baseline (speedup 1.0000x reference)
#include <cuda_runtime.h>

#define D 128
#define TM 64           // gemm rows per block
#define N_NODES 100000
#define E_MAX 1600000

// ---------------------------------------------------------------------------
// Device scratch
// ---------------------------------------------------------------------------
__device__ float g_wz[N_NODES * D];      // wz = z @ W.T + b        (51.2 MB)
__device__ float g_Wt[D * D];            // W transposed (k-major)  (64 KB)
__device__ int   g_cnt[N_NODES];         // histogram / scatter cursors
__device__ int   g_ptr[N_NODES + 1];     // CSR row_ptr by dst
__device__ int2  g_edges[E_MAX];         // (src, orig_e) grouped by dst (12.8 MB)
__device__ int   g_idx64;                // 1 if edge_index is int64

// ---------------------------------------------------------------------------
// Prep: zero counters, transpose W (once, so gemm smem fills are conflict-
// free), detect edge_index width. int64 samples all lie in [0,N); int32 read
// as int64 packs two indices and only looks valid if the high half is 0
// (p ~ 1e-5 per sample, 64 samples -> certain). Deterministic.
// ---------------------------------------------------------------------------
__global__ void __launch_bounds__(256) prep_kernel(const float* __restrict__ W,
                                                   const long long* __restrict__ ei64,
                                                   int E) {
    const int idx = blockIdx.x * 256 + threadIdx.x;
    if (idx < N_NODES) g_cnt[idx] = 0;
    if (idx < D * D) {
        const int c = idx >> 7, k = idx & 127;
        g_Wt[k * D + c] = W[idx];
    }
    if (idx == 0) {
        int all_valid = 1;
        const int step = E > 64 ? E / 64 : 1;
        for (int i = 0; i < 64; i++) {
            long long v = ei64[(long long)(i * step) % E];
            if (v < 0 || v >= N_NODES) { all_valid = 0; break; }
        }
        g_idx64 = all_valid;
    }
}

// ---------------------------------------------------------------------------
// Histogram of dst
// ---------------------------------------------------------------------------
__global__ void __launch_bounds__(256) hist_kernel(const void* __restrict__ ei_raw, int E) {
    const int i = blockIdx.x * 256 + threadIdx.x;
    if (i >= E) return;
    const int d = g_idx64 ? (int)((const long long*)ei_raw)[(long long)E + i]
                          : ((const int*)ei_raw)[E + i];
    atomicAdd(&g_cnt[d], 1);
}

// ---------------------------------------------------------------------------
// Single-block exclusive scan over g_cnt -> g_ptr; g_cnt becomes the scatter
// cursor (same exclusive values). 1024 threads, ~98 elements each.
// ---------------------------------------------------------------------------
__global__ void __launch_bounds__(1024) scan_kernel() {
    __shared__ int warp_sums[32];
    const int t = threadIdx.x;
    const int chunk = (N_NODES + 1023) / 1024;
    const int beg = t * chunk;
    const int end = min(beg + chunk, N_NODES);

    int s = 0;
    for (int i = beg; i < end; i++) s += g_cnt[i];

    const int lane = t & 31, wid = t >> 5;
    int v = s;
    #pragma unroll
    for (int off = 1; off < 32; off <<= 1) {
        int n = __shfl_up_sync(0xffffffffu, v, off);
        if (lane >= off) v += n;
    }
    if (lane == 31) warp_sums[wid] = v;
    __syncthreads();
    if (wid == 0) {
        int wv = warp_sums[lane];
        #pragma unroll
        for (int off = 1; off < 32; off <<= 1) {
            int n = __shfl_up_sync(0xffffffffu, wv, off);
            if (lane >= off) wv += n;
        }
        warp_sums[lane] = wv;
    }
    __syncthreads();

    int run = (v - s) + (wid > 0 ? warp_sums[wid - 1] : 0);  // exclusive base
    for (int i = beg; i < end; i++) {
        const int c = g_cnt[i];
        g_ptr[i] = run;
        g_cnt[i] = run;      // scatter cursor
        run += c;
    }
    if (t == 1023) g_ptr[N_NODES] = run;   // == E
}

// ---------------------------------------------------------------------------
// Scatter edges into dst-grouped order (order within a run is arbitrary;
// per-edge results are order-independent -> deterministic output).
// ---------------------------------------------------------------------------
__global__ void __launch_bounds__(256) scatter_kernel(const void* __restrict__ ei_raw, int E) {
    const int i = blockIdx.x * 256 + threadIdx.x;
    if (i >= E) return;
    int s, d;
    if (g_idx64) {
        const long long* ei = (const long long*)ei_raw;
        s = (int)ei[i];
        d = (int)ei[(long long)E + i];
    } else {
        const int* ei = (const int*)ei_raw;
        s = ei[i];
        d = ei[E + i];
    }
    const int p = atomicAdd(&g_cnt[d], 1);
    g_edges[p] = make_int2(s, i);
}

// ---------------------------------------------------------------------------
// GEMM: wz[n][o] = sum_k z[n][k] * W[o][k] + b[o]
// 256 threads, 64 rows x 128 cols per block. Thread tile 8 rows x 4 cols:
// 12 smem loads (48B) per 32 FMAs = 1.5 B/FMA < 2 B/FMA crossbar budget
// -> FMA-bound. smem k-major: W reads are float4 conflict-free, z reads are
// warp-broadcast.
// ---------------------------------------------------------------------------
__global__ void __launch_bounds__(256) gemm_kernel(const float* __restrict__ z,
                                                   const float* __restrict__ b,
                                                   int n_rows) {
    extern __shared__ float sh[];
    float* shW = sh;                 // [128][132] k-major
    float* shZ = sh + D * 132;       // [128][68]  k-major

    const int t = threadIdx.x;
    const int row0 = blockIdx.x * TM;

    // Wt fill: idx -> k=idx>>7, c=idx&127; write k*132+c: consecutive t ->
    // consecutive c -> conflict-free. Read of g_Wt coalesced.
    #pragma unroll 8
    for (int i = 0; i < D * D / 256; i++) {
        const int idx = t + i * 256;
        shW[(idx >> 7) * 132 + (idx & 127)] = g_Wt[idx];
    }
    // Z fill (transposing): gmem read coalesced; smem write 4-way conflicted
    // (stride 68) -- amortized over the k-loop.
    #pragma unroll 8
    for (int i = 0; i < TM * D / 256; i++) {
        const int idx = t + i * 256;
        const int r = idx >> 7, k = idx & 127;
        int row = row0 + r; if (row >= n_rows) row = n_rows - 1;
        shZ[k * 68 + r] = z[(size_t)row * D + k];
    }
    __syncthreads();

    const int c0 = (t & 31) * 4;
    const int r0 = (t >> 5) * 8;

    float acc[8][4];
    #pragma unroll
    for (int r = 0; r < 8; r++)
        #pragma unroll
        for (int c = 0; c < 4; c++) acc[r][c] = 0.0f;

    #pragma unroll 4
    for (int k = 0; k < D; k++) {
        const float4 wv = *(const float4*)&shW[k * 132 + c0];
        const float4 z0 = *(const float4*)&shZ[k * 68 + r0];
        const float4 z1 = *(const float4*)&shZ[k * 68 + r0 + 4];
        const float zr[8] = {z0.x, z0.y, z0.z, z0.w, z1.x, z1.y, z1.z, z1.w};
        #pragma unroll
        for (int r = 0; r < 8; r++) {
            acc[r][0] = fmaf(zr[r], wv.x, acc[r][0]);
            acc[r][1] = fmaf(zr[r], wv.y, acc[r][1]);
            acc[r][2] = fmaf(zr[r], wv.z, acc[r][2]);
            acc[r][3] = fmaf(zr[r], wv.w, acc[r][3]);
        }
    }

    const float4 bv = *(const float4*)&b[c0];
    #pragma unroll
    for (int r = 0; r < 8; r++) {
        const int row = row0 + r0 + r;
        if (row < n_rows) {
            float4 o;
            o.x = acc[r][0] + bv.x; o.y = acc[r][1] + bv.y;
            o.z = acc[r][2] + bv.z; o.w = acc[r][3] + bv.w;
            *(float4*)&g_wz[(size_t)row * D + c0] = o;
        }
    }
}

// ---------------------------------------------------------------------------
// Edge compute: warp per dst node. wz[dst] loaded ONCE into registers and
// reused for the whole run (~16 edges) -> gathered traffic drops from
// 1.64 GB to ~0.87 GB. 4 edges in flight per iteration for MLP.
// ---------------------------------------------------------------------------
__global__ void __launch_bounds__(256) edge_kernel(const float* __restrict__ z,
                                                   float* __restrict__ out) {
    const int node = (int)((blockIdx.x * 256u + threadIdx.x) >> 5);
    const int lane = threadIdx.x & 31;
    if (node >= N_NODES) return;

    const int beg = g_ptr[node];
    const int end = g_ptr[node + 1];
    if (beg == end) return;

    const float4 wv = ((const float4*)(g_wz + (size_t)node * D))[lane];

    for (int e = beg; e < end; e += 4) {
        const int m = min(4, end - e);
        int2 ed[4];
        #pragma unroll
        for (int k = 0; k < 4; k++)
            ed[k] = g_edges[e + (k < m ? k : 0)];

        float4 a[4];
        #pragma unroll
        for (int k = 0; k < 4; k++)
            a[k] = ((const float4*)(z + (size_t)ed[k].x * D))[lane];

        float v[4];
        #pragma unroll
        for (int k = 0; k < 4; k++)
            v[k] = a[k].x * wv.x + a[k].y * wv.y + a[k].z * wv.z + a[k].w * wv.w;

        #pragma unroll
        for (int off = 16; off > 0; off >>= 1) {
            #pragma unroll
            for (int k = 0; k < 4; k++)
                v[k] += __shfl_xor_sync(0xffffffffu, v[k], off);
        }

        if (lane < m) {
            const float vv = (lane == 0) ? v[0] : (lane == 1) ? v[1]
                           : (lane == 2) ? v[2] : v[3];
            out[ed[lane].y] = 1.0f / (1.0f + __expf(-vv));
        }
    }
}

// ---------------------------------------------------------------------------
// Launch. Inputs: z [N*D f32], edge_index [2*E int32-or-int64], W [D*D], b [D].
// Output: [E] f32.
// ---------------------------------------------------------------------------
extern "C" void kernel_launch(void* const* d_in, const int* in_sizes, int n_in,
                              void* d_out, int out_size) {
    const float* z  = (const float*)d_in[0];
    const void*  ei = d_in[1];
    const float* W  = (const float*)d_in[2];
    const float* b  = (const float*)d_in[3];
    float* out = (float*)d_out;

    const int E = out_size;
    const int n_rows = in_sizes[0] / D;

    const int prep_blocks = (N_NODES + 255) / 256;          // covers D*D too
    prep_kernel<<<prep_blocks, 256>>>(W, (const long long*)ei, E);

    const int eb = (E + 255) / 256;
    hist_kernel<<<eb, 256>>>(ei, E);
    scan_kernel<<<1, 1024>>>();
    scatter_kernel<<<eb, 256>>>(ei, E);

    const int smem = (D * 132 + D * 68) * (int)sizeof(float);   // 100 KB
    cudaFuncSetAttribute(gemm_kernel, cudaFuncAttributeMaxDynamicSharedMemorySize, smem);
    gemm_kernel<<<(n_rows + TM - 1) / TM, 256, smem>>>(z, b, n_rows);

    const int warps = N_NODES;                               // warp per dst node
    edge_kernel<<<(warps * 32 + 255) / 256, 256>>>(z, out);
}

// round 5
// speedup vs baseline: 1.4985x; 1.4985x over previous
#include <cuda_runtime.h>

#define D 128
#define TM 64           // gemm rows per block
#define N_NODES 100000
#define EPW 4           // edges per warp in edge kernel

// Scratch for wz = z @ W.T + b  (100000 x 128 fp32 = 51.2 MB)
__device__ float g_wz[N_NODES * D];
// W transposed to k-major once (64 KB) so gemm smem fills are conflict-free
__device__ float g_Wt[D * D];
// 1 if edge_index buffer is int64, 0 if int32
__device__ int g_idx64;

// ---------------------------------------------------------------------------
// Tiny prep: transpose W, detect edge_index width (int64 samples all lie in
// [0,N); int32 read as int64 packs two indices and only looks valid when the
// high half is 0, p ~ 1e-5 per sample; 64 samples -> certain). Deterministic.
// ---------------------------------------------------------------------------
__global__ void __launch_bounds__(256) prep_kernel(const float* __restrict__ W,
                                                   const long long* __restrict__ ei64,
                                                   int E) {
    const int idx = blockIdx.x * 256 + threadIdx.x;
    if (idx < D * D) {
        const int c = idx >> 7, k = idx & 127;
        g_Wt[k * D + c] = W[idx];
    }
    if (idx == 0) {
        int all_valid = 1;
        const int step = E > 64 ? E / 64 : 1;
        for (int i = 0; i < 64; i++) {
            long long v = ei64[(long long)(i * step) % E];
            if (v < 0 || v >= N_NODES) { all_valid = 0; break; }
        }
        g_idx64 = all_valid;
    }
}

// ---------------------------------------------------------------------------
// GEMM: wz[n][o] = sum_k z[n][k] * W[o][k] + b[o]
// 256 threads, 64 rows x 128 cols per block. Thread tile 8 rows x 4 cols:
// 3 LDS.128 per thread per k (48 B) for 32 FMAs = 1.5 B/FMA < 2 B/FMA
// crossbar budget -> FMA-issue-bound. smem is k-major: W reads are float4
// conflict-free across the warp, z reads are 16B broadcasts.
// ---------------------------------------------------------------------------
__global__ void __launch_bounds__(256, 2) gemm_kernel(const float* __restrict__ z,
                                                      const float* __restrict__ b,
                                                      int n_rows) {
    extern __shared__ float sh[];
    float* shW = sh;                 // [128][132] k-major  (67.6 KB)
    float* shZ = sh + D * 132;       // [128][68]  k-major  (34.8 KB)

    const int t = threadIdx.x;
    const int row0 = blockIdx.x * TM;

    // W fill: consecutive t -> consecutive c within a k row -> conflict-free.
    #pragma unroll 8
    for (int i = 0; i < D * D / 256; i++) {
        const int idx = t + i * 256;
        shW[(idx >> 7) * 132 + (idx & 127)] = g_Wt[idx];
    }
    // Z fill (transposing): gmem read coalesced; smem write stride 68 is
    // 4-way conflicted but only 32 iterations -- negligible.
    #pragma unroll 8
    for (int i = 0; i < TM * D / 256; i++) {
        const int idx = t + i * 256;
        const int r = idx >> 7, k = idx & 127;
        int row = row0 + r; if (row >= n_rows) row = n_rows - 1;
        shZ[k * 68 + r] = z[(size_t)row * D + k];
    }
    __syncthreads();

    const int c0 = (t & 31) * 4;     // 4 output cols
    const int r0 = (t >> 5) * 8;     // 8 output rows

    float acc[8][4];
    #pragma unroll
    for (int r = 0; r < 8; r++)
        #pragma unroll
        for (int c = 0; c < 4; c++) acc[r][c] = 0.0f;

    #pragma unroll 4
    for (int k = 0; k < D; k++) {
        const float4 wv = *(const float4*)&shW[k * 132 + c0];
        const float4 z0 = *(const float4*)&shZ[k * 68 + r0];
        const float4 z1 = *(const float4*)&shZ[k * 68 + r0 + 4];
        const float zr[8] = {z0.x, z0.y, z0.z, z0.w, z1.x, z1.y, z1.z, z1.w};
        #pragma unroll
        for (int r = 0; r < 8; r++) {
            acc[r][0] = fmaf(zr[r], wv.x, acc[r][0]);
            acc[r][1] = fmaf(zr[r], wv.y, acc[r][1]);
            acc[r][2] = fmaf(zr[r], wv.z, acc[r][2]);
            acc[r][3] = fmaf(zr[r], wv.w, acc[r][3]);
        }
    }

    const float4 bv = *(const float4*)&b[c0];
    #pragma unroll
    for (int r = 0; r < 8; r++) {
        const int row = row0 + r0 + r;
        if (row < n_rows) {
            float4 o;
            o.x = acc[r][0] + bv.x; o.y = acc[r][1] + bv.y;
            o.z = acc[r][2] + bv.z; o.w = acc[r][3] + bv.w;
            *(float4*)&g_wz[(size_t)row * D + c0] = o;
        }
    }
}

// ---------------------------------------------------------------------------
// Edge compute (measured 145 us in R3): out[e] = sigmoid(dot(z[src], wz[dst]))
// One warp handles EPW=4 consecutive edges: 8 independent LDG.128 in flight
// per warp, interleaved butterfly reductions. Lane l covers float4 l of each
// 128-float row (512 B row, fully coalesced).
// ---------------------------------------------------------------------------
__global__ void __launch_bounds__(512) edge_kernel(const float* __restrict__ z,
                                                   const void* __restrict__ ei_raw,
                                                   float* __restrict__ out,
                                                   int E) {
    const int warp = (int)((blockIdx.x * 512u + threadIdx.x) >> 5);
    const int lane = threadIdx.x & 31;
    const long long e0 = (long long)warp * EPW;
    if (e0 >= E) return;

    int src[EPW], dst[EPW];
    if (g_idx64) {
        const long long* ei = (const long long*)ei_raw;
        #pragma unroll
        for (int k = 0; k < EPW; k++) {
            long long e = e0 + k; if (e >= E) e = E - 1;
            src[k] = (int)ei[e];
            dst[k] = (int)ei[(long long)E + e];
        }
    } else {
        const int* ei = (const int*)ei_raw;
        #pragma unroll
        for (int k = 0; k < EPW; k++) {
            long long e = e0 + k; if (e >= E) e = E - 1;
            src[k] = ei[e];
            dst[k] = ei[E + e];
        }
    }

    float4 a[EPW], w[EPW];
    #pragma unroll
    for (int k = 0; k < EPW; k++)
        a[k] = ((const float4*)(z + (size_t)src[k] * D))[lane];
    #pragma unroll
    for (int k = 0; k < EPW; k++)
        w[k] = ((const float4*)(g_wz + (size_t)dst[k] * D))[lane];

    float v[EPW];
    #pragma unroll
    for (int k = 0; k < EPW; k++)
        v[k] = a[k].x * w[k].x + a[k].y * w[k].y + a[k].z * w[k].z + a[k].w * w[k].w;

    #pragma unroll
    for (int off = 16; off > 0; off >>= 1) {
        #pragma unroll
        for (int k = 0; k < EPW; k++)
            v[k] += __shfl_xor_sync(0xffffffffu, v[k], off);
    }

    if (lane < EPW) {
        const float vv = (lane == 0) ? v[0] : (lane == 1) ? v[1] : (lane == 2) ? v[2] : v[3];
        const long long e = e0 + lane;
        if (e < E)
            out[e] = 1.0f / (1.0f + __expf(-vv));
    }
}

// ---------------------------------------------------------------------------
// Launch. Inputs: z [N*D f32], edge_index [2*E int32-or-int64], W [D*D], b [D].
// Output: [E] f32.
// ---------------------------------------------------------------------------
extern "C" void kernel_launch(void* const* d_in, const int* in_sizes, int n_in,
                              void* d_out, int out_size) {
    const float* z  = (const float*)d_in[0];
    const void*  ei = d_in[1];
    const float* W  = (const float*)d_in[2];
    const float* b  = (const float*)d_in[3];
    float* out = (float*)d_out;

    const int E = out_size;
    const int n_rows = in_sizes[0] / D;

    prep_kernel<<<(D * D + 255) / 256, 256>>>(W, (const long long*)ei, E);

    const int smem = (D * 132 + D * 68) * (int)sizeof(float);   // ~102.4 KB
    cudaFuncSetAttribute(gemm_kernel, cudaFuncAttributeMaxDynamicSharedMemorySize, smem);
    gemm_kernel<<<(n_rows + TM - 1) / TM, 256, smem>>>(z, b, n_rows);

    const int warps_needed = (E + EPW - 1) / EPW;
    const int blocks = (warps_needed + 15) / 16;   // 16 warps (512 thr) per block
    edge_kernel<<<blocks, 512>>>(z, ei, out, E);
}

// round 6
// speedup vs baseline: 1.6481x; 1.0998x over previous
#include <cuda_runtime.h>

#define D 128
#define TM 64           // gemm rows per block
#define N_NODES 100000
#define EPW 4           // edges per warp in edge kernel

// Scratch for wz = z @ W.T + b  (100000 x 128 fp32 = 51.2 MB)
__device__ float g_wz[N_NODES * D];
// 1 if edge_index buffer is int64, 0 if int32
__device__ int g_idx64;

// Packed fp32x2 helpers (Blackwell f32x2 pipe; ptxas never emits these from C++)
#define PACK2(out, lo, hi) \
    asm("mov.b64 %0, {%1, %2};" : "=l"(out) : "f"(lo), "f"(hi))
#define UNPACK2(lo, hi, in) \
    asm("mov.b64 {%0, %1}, %2;" : "=f"(lo), "=f"(hi) : "l"(in))
#define FMA2(acc, a, b) \
    asm("fma.rn.f32x2 %0, %1, %2, %0;" : "+l"(acc) : "l"(a), "l"(b))

// ---------------------------------------------------------------------------
// GEMM: wz[n][o] = sum_k z[n][k] * W[o][k] + b[o]
// 256 threads, 64 rows x 128 cols per block, thread tile 8 rows x 4 cols.
// Inner loop uses fma.rn.f32x2: accumulators pair adjacent ROWS (which are
// adjacent floats in the k-major shZ float4 -> free register pairs); the
// per-column broadcast ww=(w_c,w_c) costs 4 mov.b64 per k on the ALU pipe.
// FMA pipe: 16 FFMA2/thread/k -> 64 cyc/SMSP/k (vs 128 scalar).
// Block 0 thread 0 also detects edge_index width (int64 samples all lie in
// [0,N); int32 read as int64 packs two indices and only looks valid when the
// high half is 0, p~1e-5/sample; 64 samples -> certain). Deterministic.
// ---------------------------------------------------------------------------
__global__ void __launch_bounds__(256, 2) gemm_kernel(const float* __restrict__ z,
                                                      const float* __restrict__ W,
                                                      const float* __restrict__ b,
                                                      const long long* __restrict__ ei64,
                                                      int E, int n_rows) {
    extern __shared__ float sh[];
    float* shW = sh;                 // [128][132] k-major  (67.6 KB)
    float* shZ = sh + D * 132;       // [128][68]  k-major  (34.8 KB)

    const int t = threadIdx.x;
    const int row0 = blockIdx.x * TM;

    if (blockIdx.x == 0 && t == 0) {
        int all_valid = 1;
        const int step = E > 64 ? E / 64 : 1;
        for (int i = 0; i < 64; i++) {
            long long v = ei64[(long long)(i * step) % E];
            if (v < 0 || v >= N_NODES) { all_valid = 0; break; }
        }
        g_idx64 = all_valid;
    }

    // W fill: gmem coalesced; smem stride-132 write is 4-way conflicted but
    // only 64 iterations -- negligible vs the 128-step main loop.
    #pragma unroll 8
    for (int i = 0; i < D * D / 256; i++) {
        const int idx = t + i * 256;
        shW[(idx & 127) * 132 + (idx >> 7)] = W[idx];
    }
    // Z fill (transposing): gmem coalesced.
    #pragma unroll 8
    for (int i = 0; i < TM * D / 256; i++) {
        const int idx = t + i * 256;
        const int r = idx >> 7, k = idx & 127;
        int row = row0 + r; if (row >= n_rows) row = n_rows - 1;
        shZ[k * 68 + r] = z[(size_t)row * D + k];
    }
    __syncthreads();

    const int c0 = (t & 31) * 4;     // 4 output cols
    const int r0 = (t >> 5) * 8;     // 8 output rows (4 packed pairs)

    unsigned long long acc2[4][4];   // [row_pair][col]
    #pragma unroll
    for (int rp = 0; rp < 4; rp++)
        #pragma unroll
        for (int c = 0; c < 4; c++) acc2[rp][c] = 0ull;

    #pragma unroll 4
    for (int k = 0; k < D; k++) {
        const float4 wv = *(const float4*)&shW[k * 132 + c0];
        const float4 z0 = *(const float4*)&shZ[k * 68 + r0];
        const float4 z1 = *(const float4*)&shZ[k * 68 + r0 + 4];

        unsigned long long ww[4], zp[4];
        PACK2(ww[0], wv.x, wv.x);
        PACK2(ww[1], wv.y, wv.y);
        PACK2(ww[2], wv.z, wv.z);
        PACK2(ww[3], wv.w, wv.w);
        PACK2(zp[0], z0.x, z0.y);
        PACK2(zp[1], z0.z, z0.w);
        PACK2(zp[2], z1.x, z1.y);
        PACK2(zp[3], z1.z, z1.w);

        #pragma unroll
        for (int rp = 0; rp < 4; rp++) {
            FMA2(acc2[rp][0], zp[rp], ww[0]);
            FMA2(acc2[rp][1], zp[rp], ww[1]);
            FMA2(acc2[rp][2], zp[rp], ww[2]);
            FMA2(acc2[rp][3], zp[rp], ww[3]);
        }
    }

    const float4 bv = *(const float4*)&b[c0];
    #pragma unroll
    for (int rp = 0; rp < 4; rp++) {
        float lo[4], hi[4];
        #pragma unroll
        for (int c = 0; c < 4; c++) UNPACK2(lo[c], hi[c], acc2[rp][c]);

        const int row_lo = row0 + r0 + 2 * rp;
        if (row_lo < n_rows) {
            float4 o;
            o.x = lo[0] + bv.x; o.y = lo[1] + bv.y;
            o.z = lo[2] + bv.z; o.w = lo[3] + bv.w;
            *(float4*)&g_wz[(size_t)row_lo * D + c0] = o;
        }
        const int row_hi = row_lo + 1;
        if (row_hi < n_rows) {
            float4 o;
            o.x = hi[0] + bv.x; o.y = hi[1] + bv.y;
            o.z = hi[2] + bv.z; o.w = hi[3] + bv.w;
            *(float4*)&g_wz[(size_t)row_hi * D + c0] = o;
        }
    }
}

// ---------------------------------------------------------------------------
// Edge compute (measured 145 us, at the LTS byte cap):
// out[e] = sigmoid(dot(z[src], wz[dst])). One warp handles EPW=4 consecutive
// edges: 8 independent LDG.128 in flight, interleaved butterfly reductions.
// Lane l covers float4 l of each 128-float row (512 B, fully coalesced).
// ---------------------------------------------------------------------------
__global__ void __launch_bounds__(512) edge_kernel(const float* __restrict__ z,
                                                   const void* __restrict__ ei_raw,
                                                   float* __restrict__ out,
                                                   int E) {
    const int warp = (int)((blockIdx.x * 512u + threadIdx.x) >> 5);
    const int lane = threadIdx.x & 31;
    const long long e0 = (long long)warp * EPW;
    if (e0 >= E) return;

    int src[EPW], dst[EPW];
    if (g_idx64) {
        const long long* ei = (const long long*)ei_raw;
        #pragma unroll
        for (int k = 0; k < EPW; k++) {
            long long e = e0 + k; if (e >= E) e = E - 1;
            src[k] = (int)ei[e];
            dst[k] = (int)ei[(long long)E + e];
        }
    } else {
        const int* ei = (const int*)ei_raw;
        #pragma unroll
        for (int k = 0; k < EPW; k++) {
            long long e = e0 + k; if (e >= E) e = E - 1;
            src[k] = ei[e];
            dst[k] = ei[E + e];
        }
    }

    float4 a[EPW], w[EPW];
    #pragma unroll
    for (int k = 0; k < EPW; k++)
        a[k] = ((const float4*)(z + (size_t)src[k] * D))[lane];
    #pragma unroll
    for (int k = 0; k < EPW; k++)
        w[k] = ((const float4*)(g_wz + (size_t)dst[k] * D))[lane];

    float v[EPW];
    #pragma unroll
    for (int k = 0; k < EPW; k++)
        v[k] = a[k].x * w[k].x + a[k].y * w[k].y + a[k].z * w[k].z + a[k].w * w[k].w;

    #pragma unroll
    for (int off = 16; off > 0; off >>= 1) {
        #pragma unroll
        for (int k = 0; k < EPW; k++)
            v[k] += __shfl_xor_sync(0xffffffffu, v[k], off);
    }

    if (lane < EPW) {
        const float vv = (lane == 0) ? v[0] : (lane == 1) ? v[1] : (lane == 2) ? v[2] : v[3];
        const long long e = e0 + lane;
        if (e < E)
            out[e] = 1.0f / (1.0f + __expf(-vv));
    }
}

// ---------------------------------------------------------------------------
// Launch. Inputs: z [N*D f32], edge_index [2*E int32-or-int64], W [D*D], b [D].
// Output: [E] f32.
// ---------------------------------------------------------------------------
extern "C" void kernel_launch(void* const* d_in, const int* in_sizes, int n_in,
                              void* d_out, int out_size) {
    const float* z  = (const float*)d_in[0];
    const void*  ei = d_in[1];
    const float* W  = (const float*)d_in[2];
    const float* b  = (const float*)d_in[3];
    float* out = (float*)d_out;

    const int E = out_size;
    const int n_rows = in_sizes[0] / D;

    const int smem = (D * 132 + D * 68) * (int)sizeof(float);   // ~102.4 KB
    cudaFuncSetAttribute(gemm_kernel, cudaFuncAttributeMaxDynamicSharedMemorySize, smem);
    gemm_kernel<<<(n_rows + TM - 1) / TM, 256, smem>>>(z, W, b,
                                                       (const long long*)ei, E, n_rows);

    const int warps_needed = (E + EPW - 1) / EPW;
    const int blocks = (warps_needed + 15) / 16;   // 16 warps (512 thr) per block
    edge_kernel<<<blocks, 512>>>(z, ei, out, E);
}

// round 7
// speedup vs baseline: 1.7289x; 1.0491x over previous
#include <cuda_runtime.h>

#define D 128
#define TM 64           // gemm rows per block
#define N_NODES 100000
#define EPW 4           // edges per warp in edge kernel

// Quantized operands for the edge phase (halved gather bytes):
__device__ short g_z16[N_NODES * D];    // z, int16 row-scaled   (25.6 MB)
__device__ short g_wz16[N_NODES * D];   // wz, int16 row-scaled  (25.6 MB)
__device__ float g_sz[N_NODES];         // per-row scale of z
__device__ float g_sw[N_NODES];         // per-row scale of wz
__device__ int   g_idx64;               // 1 if edge_index is int64

// Packed fp32x2 helpers
#define PACK2(out, lo, hi) \
    asm("mov.b64 %0, {%1, %2};" : "=l"(out) : "f"(lo), "f"(hi))
#define UNPACK2(lo, hi, in) \
    asm("mov.b64 {%0, %1}, %2;" : "=f"(lo), "=f"(hi) : "l"(in))
#define FMA2(acc, a, b) \
    asm("fma.rn.f32x2 %0, %1, %2, %0;" : "+l"(acc) : "l"(a), "l"(b))

__device__ __forceinline__ short q15(float v, float inv) {
    int q = __float2int_rn(v * inv);
    q = max(-32767, min(32767, q));
    return (short)q;
}

// ---------------------------------------------------------------------------
// z quantization: one warp per row. Butterfly row-max, scale to int15.
// Block 0 thread 0 also detects edge_index width (int64 samples all lie in
// [0,N); int32 read as int64 packs two indices and only looks valid when the
// high half is 0, p~1e-5/sample; 64 samples -> certain). Deterministic.
// ---------------------------------------------------------------------------
__global__ void __launch_bounds__(256) zquant_kernel(const float* __restrict__ z,
                                                     const long long* __restrict__ ei64,
                                                     int E, int n_rows) {
    if (blockIdx.x == 0 && threadIdx.x == 0) {
        int all_valid = 1;
        const int step = E > 64 ? E / 64 : 1;
        for (int i = 0; i < 64; i++) {
            long long v = ei64[(long long)(i * step) % E];
            if (v < 0 || v >= N_NODES) { all_valid = 0; break; }
        }
        g_idx64 = all_valid;
    }

    const int row = (int)((blockIdx.x * 256u + threadIdx.x) >> 5);
    const int lane = threadIdx.x & 31;
    if (row >= n_rows) return;

    const float4 v = ((const float4*)(z + (size_t)row * D))[lane];
    float m = fmaxf(fmaxf(fabsf(v.x), fabsf(v.y)), fmaxf(fabsf(v.z), fabsf(v.w)));
    #pragma unroll
    for (int off = 16; off > 0; off >>= 1)
        m = fmaxf(m, __shfl_xor_sync(0xffffffffu, m, off));

    const float inv = 32767.0f / fmaxf(m, 1e-30f);
    short4 q;
    q.x = q15(v.x, inv); q.y = q15(v.y, inv);
    q.z = q15(v.z, inv); q.w = q15(v.w, inv);
    ((short4*)(g_z16 + (size_t)row * D))[lane] = q;
    if (lane == 0) g_sz[row] = m * (1.0f / 32767.0f);
}

// ---------------------------------------------------------------------------
// GEMM: wz[n][o] = sum_k z[n][k] * W[o][k] + b[o], epilogue quantizes each
// row to int16 (warp owns 8 full rows: lanes 0..31 cover cols, butterfly max).
// 256 threads, 64 rows x 128 cols per block, thread tile 8 rows x 4 cols,
// inner loop in fma.rn.f32x2 over row pairs.
// ---------------------------------------------------------------------------
__global__ void __launch_bounds__(256, 2) gemm_kernel(const float* __restrict__ z,
                                                      const float* __restrict__ W,
                                                      const float* __restrict__ b,
                                                      int n_rows) {
    extern __shared__ float sh[];
    float* shW = sh;                 // [128][132] k-major
    float* shZ = sh + D * 132;       // [128][68]  k-major

    const int t = threadIdx.x;
    const int row0 = blockIdx.x * TM;

    #pragma unroll 8
    for (int i = 0; i < D * D / 256; i++) {
        const int idx = t + i * 256;
        shW[(idx & 127) * 132 + (idx >> 7)] = W[idx];
    }
    #pragma unroll 8
    for (int i = 0; i < TM * D / 256; i++) {
        const int idx = t + i * 256;
        const int r = idx >> 7, k = idx & 127;
        int row = row0 + r; if (row >= n_rows) row = n_rows - 1;
        shZ[k * 68 + r] = z[(size_t)row * D + k];
    }
    __syncthreads();

    const int c0 = (t & 31) * 4;     // 4 output cols
    const int r0 = (t >> 5) * 8;     // 8 output rows (4 packed pairs)

    unsigned long long acc2[4][4];
    #pragma unroll
    for (int rp = 0; rp < 4; rp++)
        #pragma unroll
        for (int c = 0; c < 4; c++) acc2[rp][c] = 0ull;

    #pragma unroll 4
    for (int k = 0; k < D; k++) {
        const float4 wv = *(const float4*)&shW[k * 132 + c0];
        const float4 z0 = *(const float4*)&shZ[k * 68 + r0];
        const float4 z1 = *(const float4*)&shZ[k * 68 + r0 + 4];

        unsigned long long ww[4], zp[4];
        PACK2(ww[0], wv.x, wv.x);
        PACK2(ww[1], wv.y, wv.y);
        PACK2(ww[2], wv.z, wv.z);
        PACK2(ww[3], wv.w, wv.w);
        PACK2(zp[0], z0.x, z0.y);
        PACK2(zp[1], z0.z, z0.w);
        PACK2(zp[2], z1.x, z1.y);
        PACK2(zp[3], z1.z, z1.w);

        #pragma unroll
        for (int rp = 0; rp < 4; rp++) {
            FMA2(acc2[rp][0], zp[rp], ww[0]);
            FMA2(acc2[rp][1], zp[rp], ww[1]);
            FMA2(acc2[rp][2], zp[rp], ww[2]);
            FMA2(acc2[rp][3], zp[rp], ww[3]);
        }
    }

    // Epilogue: bias, per-row max across the warp, quantize, store int16.
    const float4 bv = *(const float4*)&b[c0];
    float vals[8][4];
    #pragma unroll
    for (int rp = 0; rp < 4; rp++) {
        float lo[4], hi[4];
        #pragma unroll
        for (int c = 0; c < 4; c++) UNPACK2(lo[c], hi[c], acc2[rp][c]);
        vals[2 * rp][0] = lo[0] + bv.x; vals[2 * rp][1] = lo[1] + bv.y;
        vals[2 * rp][2] = lo[2] + bv.z; vals[2 * rp][3] = lo[3] + bv.w;
        vals[2 * rp + 1][0] = hi[0] + bv.x; vals[2 * rp + 1][1] = hi[1] + bv.y;
        vals[2 * rp + 1][2] = hi[2] + bv.z; vals[2 * rp + 1][3] = hi[3] + bv.w;
    }

    const int lane = t & 31;
    #pragma unroll
    for (int r = 0; r < 8; r++) {
        float m = fmaxf(fmaxf(fabsf(vals[r][0]), fabsf(vals[r][1])),
                        fmaxf(fabsf(vals[r][2]), fabsf(vals[r][3])));
        #pragma unroll
        for (int off = 16; off > 0; off >>= 1)
            m = fmaxf(m, __shfl_xor_sync(0xffffffffu, m, off));

        const float inv = 32767.0f / fmaxf(m, 1e-30f);
        const int row = row0 + r0 + r;
        if (row < n_rows) {
            short4 q;
            q.x = q15(vals[r][0], inv); q.y = q15(vals[r][1], inv);
            q.z = q15(vals[r][2], inv); q.w = q15(vals[r][3], inv);
            *(short4*)&g_wz16[(size_t)row * D + c0] = q;
            if (lane == 0) g_sw[row] = m * (1.0f / 32767.0f);
        }
    }
}

// ---------------------------------------------------------------------------
// Edge compute: out[e] = sigmoid( sz[src]*sw[dst] * dot(z16[src], wz16[dst]) )
// One warp handles 4 edges; lane l loads short4 l of each 128-int16 row
// (256 B row, fully coalesced LDG.64). Scales prefetched by lanes 0..3.
// ---------------------------------------------------------------------------
__global__ void __launch_bounds__(512) edge_kernel(const void* __restrict__ ei_raw,
                                                   float* __restrict__ out,
                                                   int E) {
    const int warp = (int)((blockIdx.x * 512u + threadIdx.x) >> 5);
    const int lane = threadIdx.x & 31;
    const long long e0 = (long long)warp * EPW;
    if (e0 >= E) return;

    int src[EPW], dst[EPW];
    if (g_idx64) {
        const long long* ei = (const long long*)ei_raw;
        #pragma unroll
        for (int k = 0; k < EPW; k++) {
            long long e = e0 + k; if (e >= E) e = E - 1;
            src[k] = (int)ei[e];
            dst[k] = (int)ei[(long long)E + e];
        }
    } else {
        const int* ei = (const int*)ei_raw;
        #pragma unroll
        for (int k = 0; k < EPW; k++) {
            long long e = e0 + k; if (e >= E) e = E - 1;
            src[k] = ei[e];
            dst[k] = ei[E + e];
        }
    }

    // Prefetch scales early (lanes 0..3, one edge each).
    float sc = 0.0f;
    if (lane < EPW)
        sc = g_sz[src[lane]] * g_sw[dst[lane]];

    short4 a[EPW], w[EPW];
    #pragma unroll
    for (int k = 0; k < EPW; k++)
        a[k] = ((const short4*)(g_z16 + (size_t)src[k] * D))[lane];
    #pragma unroll
    for (int k = 0; k < EPW; k++)
        w[k] = ((const short4*)(g_wz16 + (size_t)dst[k] * D))[lane];

    float v[EPW];
    #pragma unroll
    for (int k = 0; k < EPW; k++) {
        float s = (float)a[k].x * (float)w[k].x;
        s = fmaf((float)a[k].y, (float)w[k].y, s);
        s = fmaf((float)a[k].z, (float)w[k].z, s);
        s = fmaf((float)a[k].w, (float)w[k].w, s);
        v[k] = s;
    }

    #pragma unroll
    for (int off = 16; off > 0; off >>= 1) {
        #pragma unroll
        for (int k = 0; k < EPW; k++)
            v[k] += __shfl_xor_sync(0xffffffffu, v[k], off);
    }

    if (lane < EPW) {
        const float vv = (lane == 0) ? v[0] : (lane == 1) ? v[1] : (lane == 2) ? v[2] : v[3];
        const long long e = e0 + lane;
        if (e < E)
            out[e] = 1.0f / (1.0f + __expf(-vv * sc));
    }
}

// ---------------------------------------------------------------------------
// Launch. Inputs: z [N*D f32], edge_index [2*E int32-or-int64], W [D*D], b [D].
// Output: [E] f32.
// ---------------------------------------------------------------------------
extern "C" void kernel_launch(void* const* d_in, const int* in_sizes, int n_in,
                              void* d_out, int out_size) {
    const float* z  = (const float*)d_in[0];
    const void*  ei = d_in[1];
    const float* W  = (const float*)d_in[2];
    const float* b  = (const float*)d_in[3];
    float* out = (float*)d_out;

    const int E = out_size;
    const int n_rows = in_sizes[0] / D;

    zquant_kernel<<<(n_rows * 32 + 255) / 256, 256>>>(z, (const long long*)ei, E, n_rows);

    const int smem = (D * 132 + D * 68) * (int)sizeof(float);   // ~102.4 KB
    cudaFuncSetAttribute(gemm_kernel, cudaFuncAttributeMaxDynamicSharedMemorySize, smem);
    gemm_kernel<<<(n_rows + TM - 1) / TM, 256, smem>>>(z, W, b, n_rows);

    const int warps_needed = (E + EPW - 1) / EPW;
    const int blocks = (warps_needed + 15) / 16;   // 16 warps (512 thr) per block
    edge_kernel<<<blocks, 512>>>(ei, out, E);
}